// round 10
// baseline (speedup 1.0000x reference)
#include <cuda_runtime.h>
#include <cuda_fp16.h>
#include <cstdint>

#define NN 512
#define HH 8
#define RDC 4096
#define MRN 65536
#define DPL 2097152   // one dots plane
#define ASTG_H 5120   // halves per A stage (128*40)

__device__ __align__(16) __half g_xh  [MRN * 128];
__device__ __align__(16) __half g_wt  [896 * 128];
__device__ __align__(16) __half g_woutt[128 * 256];
__device__ __align__(16) __half g_qh  [HH * NN * RDC];
__device__ __align__(16) __half g_kh  [HH * NN * RDC];
__device__ __align__(16) __half g_vh  [HH * NN * RDC];
__device__ __align__(16) __half g_ph  [HH * NN * NN];
__device__ __align__(16) __half g_o2  [MRN * 256];
__device__ __align__(16) float  g_dots[4 * DPL];
__device__ __align__(16) float  g_pbh [HH * NN * NN];
__device__ __align__(16) float  g_ksw [MRN * 128];
__device__ __align__(16) float  g_qsw [NN * 128];
__device__ __align__(16) float  g_wrow[NN * HH * 128];

__device__ __forceinline__ uint32_t smem_u32(const void* p) {
    uint32_t a;
    asm("{ .reg .u64 t; cvta.to.shared.u64 t, %1; cvt.u32.u64 %0, t; }" : "=r"(a) : "l"(p));
    return a;
}
__device__ __forceinline__ void ldm4(uint32_t* r, uint32_t addr) {
    asm volatile("ldmatrix.sync.aligned.m8n8.x4.shared.b16 {%0,%1,%2,%3}, [%4];"
                 : "=r"(r[0]), "=r"(r[1]), "=r"(r[2]), "=r"(r[3]) : "r"(addr));
}
__device__ __forceinline__ void ldm4t(uint32_t* r, uint32_t addr) {
    asm volatile("ldmatrix.sync.aligned.m8n8.x4.trans.shared.b16 {%0,%1,%2,%3}, [%4];"
                 : "=r"(r[0]), "=r"(r[1]), "=r"(r[2]), "=r"(r[3]) : "r"(addr));
}
__device__ __forceinline__ void mma16(float* c, const uint32_t* a, const uint32_t* b) {
    asm volatile("mma.sync.aligned.m16n8k16.row.col.f32.f16.f16.f32 "
        "{%0,%1,%2,%3},{%4,%5,%6,%7},{%8,%9},{%0,%1,%2,%3};"
        : "+f"(c[0]), "+f"(c[1]), "+f"(c[2]), "+f"(c[3])
        : "r"(a[0]), "r"(a[1]), "r"(a[2]), "r"(a[3]), "r"(b[0]), "r"(b[1]));
}
#define CPA16(dst, src) \
    asm volatile("cp.async.cg.shared.global [%0], [%1], 16;" :: "r"(dst), "l"(src) : "memory")

// ============================================================================
// fp16 GEMM: block 128xBN, 8 warps (warp 64 x BN/4), ktile 32, 3-stage.
// Loop (proven R8): wait -> barrier -> compute(kt) -> issue(kt+2).
// MODE: 0=qkv, 1=dots(split-K=4), 2=O trans-B, 3=out, 4=ksw
// ============================================================================
template<int MODE, int KT, int BN>
__global__ __launch_bounds__(256) void g16(const float* __restrict__ auxA,
                                           float* __restrict__ outp) {
    constexpr int NT = BN / 32;        // nt tiles per warp (4 or 8)
    constexpr int NP = BN / 64;        // B ldm4 per kk (2 or 4)
    constexpr int BSTG_H = BN * 40;    // halves per B stage
    extern __shared__ __half sh[];
    __half* AsB = sh;
    __half* BsB = sh + 3 * ASTG_H;
    const int t = threadIdx.x, lane = t & 31, warp = t >> 5;
    const int bx = blockIdx.x, by = blockIdx.y;
    const int h = (MODE == 1) ? (blockIdx.z & 7) : blockIdx.z;
    const int split = (MODE == 1) ? (blockIdx.z >> 3) : 0;

    const __half *A, *B; int lda, ldb;
    if (MODE == 0)      { A = g_xh + (size_t)by * 128 * 128; lda = 128;
                          B = g_wt + (size_t)bx * BN * 128;  ldb = 128; }
    else if (MODE == 4) { A = g_xh + (size_t)by * 128 * 128; lda = 128;
                          B = g_wt + (size_t)768 * 128;      ldb = 128; }
    else if (MODE == 1) { A = g_qh + ((size_t)h * 512 + by * 128) * 4096 + split * 1024; lda = 4096;
                          B = g_kh + ((size_t)h * 512 + bx * BN) * 4096 + split * 1024;  ldb = 4096; }
    else if (MODE == 2) { A = g_ph + ((size_t)h * 512 + by * 128) * 512; lda = 512;
                          B = g_vh + (size_t)h * 512 * 4096 + bx * BN;   ldb = 4096; }
    else                { A = g_o2 + (size_t)by * 128 * 256; lda = 256;
                          B = g_woutt;                       ldb = 256; }

    auto cpst = [&](int st, int k0) {
        uint32_t da = smem_u32(AsB + st * ASTG_H), db = smem_u32(BsB + st * BSTG_H);
#pragma unroll
        for (int c = t; c < 512; c += 256) {
            int row = c >> 2, col = c & 3;
            CPA16(da + row * 80 + col * 16, A + (size_t)row * lda + k0 + col * 8);
        }
        if (MODE == 2) {
            constexpr int RPC = BN / 8;       // 16B chunks per k-row
#pragma unroll
            for (int c = t; c < 32 * RPC; c += 256) {
                int row = c / RPC, col = c % RPC;
                CPA16(db + row * (BN * 2 + 16) + col * 16, B + (size_t)(k0 + row) * ldb + col * 8);
            }
        } else {
#pragma unroll
            for (int c = t; c < BN * 4; c += 256) {
                int row = c >> 2, col = c & 3;
                CPA16(db + row * 80 + col * 16, B + (size_t)row * ldb + k0 + col * 8);
            }
        }
        asm volatile("cp.async.commit_group;" ::: "memory");
    };

    float acc[4][NT][4] = {};
    const int wm0 = (warp >> 2) * 64, wn0 = (warp & 3) * (BN / 4);
    const int q = lane >> 3;

    cpst(0, 0);
    if (KT > 1) cpst(1, 32);
    int st = 0;
    for (int kt = 0; kt < KT; kt++) {
        if (kt + 1 < KT) asm volatile("cp.async.wait_group 1;" ::: "memory");
        else             asm volatile("cp.async.wait_group 0;" ::: "memory");
        __syncthreads();
        uint32_t ab = smem_u32(AsB + st * ASTG_H), bb = smem_u32(BsB + st * BSTG_H);
#pragma unroll
        for (int kk = 0; kk < 32; kk += 16) {
            uint32_t af[4][4], bf[NP][4];
#pragma unroll
            for (int mt = 0; mt < 4; mt++)
                ldm4(af[mt], ab + (wm0 + mt * 16 + (lane & 15)) * 80 + (kk + (lane >> 4) * 8) * 2);
#pragma unroll
            for (int np = 0; np < NP; np++) {
                if (MODE == 2)
                    ldm4t(bf[np], bb + (kk + (q & 1) * 8 + (lane & 7)) * (BN * 2 + 16)
                                     + (wn0 + np * 16 + (q >> 1) * 8) * 2);
                else
                    ldm4(bf[np], bb + (wn0 + np * 16 + (q >> 1) * 8 + (lane & 7)) * 80
                                    + (kk + (q & 1) * 8) * 2);
            }
#pragma unroll
            for (int mt = 0; mt < 4; mt++)
#pragma unroll
                for (int nt = 0; nt < NT; nt++)
                    mma16(acc[mt][nt], af[mt], &bf[nt >> 1][(nt & 1) * 2]);
        }
        if (kt + 2 < KT) {
            int ns = st + 2; if (ns >= 3) ns -= 3;
            cpst(ns, (kt + 2) * 32);
        }
        st = (st == 2) ? 0 : st + 1;
    }

#pragma unroll
    for (int mt = 0; mt < 4; mt++)
#pragma unroll
        for (int nt = 0; nt < NT; nt++)
#pragma unroll
            for (int hf = 0; hf < 2; hf++) {
                int mrow = wm0 + mt * 16 + (lane >> 2) + hf * 8;
                int ncol = wn0 + nt * 8 + (lane & 3) * 2;
                float v0 = acc[mt][nt][hf * 2], v1 = acc[mt][nt][hf * 2 + 1];
                if (MODE == 0) {
                    int m = by * 128 + mrow, c = bx * BN + ncol;
                    int r = m >> 9, n = m & 511;
                    if (c < 256) {
                        int hh = c >> 5, d = c & 31;
                        float w = g_wrow[(n * 8 + hh) * 128 + r];
                        *reinterpret_cast<__half2*>(
                            &g_qh[((size_t)(hh * 512 + n)) * 4096 + r * 32 + d]) =
                            __floats2half2_rn(v0 * w, v1 * w);
                    } else if (c < 512) {
                        int cc = c - 256, hh = cc >> 5, d = cc & 31;
                        *reinterpret_cast<__half2*>(
                            &g_kh[((size_t)(hh * 512 + n)) * 4096 + r * 32 + d]) =
                            __floats2half2_rn(v0, v1);
                    } else {
                        int cc = c - 512, hh = cc >> 5, d = cc & 31;
                        *reinterpret_cast<__half2*>(
                            &g_vh[((size_t)(hh * 512 + n)) * 4096 + r * 32 + d]) =
                            __floats2half2_rn(v0, v1);
                    }
                } else if (MODE == 4) {
                    int m = by * 128 + mrow;
                    g_ksw[(size_t)m * 128 + ncol]     = v0 + auxA[ncol];
                    g_ksw[(size_t)m * 128 + ncol + 1] = v1 + auxA[ncol + 1];
                } else if (MODE == 1) {
                    int i = by * 128 + mrow, j = bx * BN + ncol;
                    size_t off = (size_t)split * DPL + ((size_t)h * 512 + i) * 512 + j;
                    g_dots[off]     = v0;
                    g_dots[off + 1] = v1;
                } else if (MODE == 2) {
                    int i = by * 128 + mrow, tcol = bx * BN + ncol;
                    int r = tcol >> 5, d = tcol & 31;
                    *reinterpret_cast<__half2*>(
                        &g_o2[((size_t)r * 512 + i) * 256 + h * 32 + d]) =
                        __floats2half2_rn(v0, v1);
                } else {
                    int m = by * 128 + mrow;
                    outp[(size_t)m * 128 + ncol]     = v0 + auxA[ncol];
                    outp[(size_t)m * 128 + ncol + 1] = v1 + auxA[ncol + 1];
                }
            }
}

// ============================================================================
__global__ void conv_x(const float* __restrict__ x) {
    size_t i = ((size_t)blockIdx.x * 256 + threadIdx.x) * 4;
    float4 v = *reinterpret_cast<const float4*>(x + i);
    __half2* d = reinterpret_cast<__half2*>(&g_xh[i]);
    d[0] = __floats2half2_rn(v.x, v.y);
    d[1] = __floats2half2_rn(v.z, v.w);
}

__global__ void conv_w(const float* __restrict__ Wq, const float* __restrict__ Wkv,
                       const float* __restrict__ Wk_sw, const float* __restrict__ Wout) {
    int g = blockIdx.x * 256 + threadIdx.x;
    if (g < 114688) {
        int row = g >> 7, k = g & 127;
        float v;
        if (row < 256)      v = Wq[k * 256 + row];
        else if (row < 768) v = Wkv[k * 512 + (row - 256)];
        else                v = Wk_sw[k * 128 + (row - 768)];
        g_wt[g] = __float2half_rn(v);
    } else {
        int g2 = g - 114688;
        int c = g2 >> 8, k = g2 & 255;
        g_woutt[g2] = __float2half_rn(Wout[k * 128 + c]);
    }
}

__global__ void qsw_kernel(const float* __restrict__ x, const float* __restrict__ Wq_sw,
                           const float* __restrict__ bq_sw) {
    int n = blockIdx.x, c = threadIdx.x;
    __shared__ float xr[128];
    xr[c] = x[(size_t)n * 128 + c];
    __syncthreads();
    float acc = bq_sw[c];
#pragma unroll 8
    for (int k = 0; k < 128; k++) acc += xr[k] * Wq_sw[k * 128 + c];
    g_qsw[n * 128 + c] = acc;
}

__global__ void sw_reduce_kernel() {
    int m = blockIdx.x, r = m >> 9, n = m & 511, c = threadIdx.x;
    float prod = g_ksw[(size_t)m * 128 + c] * g_qsw[n * 128 + c];
#pragma unroll
    for (int o = 8; o; o >>= 1) prod += __shfl_down_sync(0xffffffffu, prod, o, 16);
    if ((c & 15) == 0) g_wrow[(n * 8 + (c >> 4)) * 128 + r] = prod * 0.25f;
}

__global__ void wrow_softmax_kernel() {
    int row = blockIdx.x, t = threadIdx.x;
    float v = g_wrow[(size_t)row * 128 + t];
    __shared__ float sm[128];
    sm[t] = v; __syncthreads();
#pragma unroll
    for (int s = 64; s > 0; s >>= 1) { if (t < s) sm[t] = fmaxf(sm[t], sm[t + s]); __syncthreads(); }
    float mx = sm[0]; __syncthreads();
    float e = expf(v - mx);
    sm[t] = e; __syncthreads();
#pragma unroll
    for (int s = 64; s > 0; s >>= 1) { if (t < s) sm[t] += sm[t + s]; __syncthreads(); }
    g_wrow[(size_t)row * 128 + t] = e / sm[0];
}

__global__ void pbh_kernel(const float* __restrict__ pair_bias, const float* __restrict__ ln_g,
                           const float* __restrict__ ln_b, const float* __restrict__ Wpair) {
    int warp = threadIdx.x >> 5, lane = threadIdx.x & 31;
    int idx = blockIdx.x * 8 + warp;
    int i = idx >> 9, j = idx & 511;
    float4 v = *reinterpret_cast<const float4*>(&pair_bias[(size_t)idx * 128 + lane * 4]);
    float s  = v.x + v.y + v.z + v.w;
    float sq = v.x * v.x + v.y * v.y + v.z * v.z + v.w * v.w;
#pragma unroll
    for (int o = 16; o; o >>= 1) {
        s  += __shfl_xor_sync(0xffffffffu, s, o);
        sq += __shfl_xor_sync(0xffffffffu, sq, o);
    }
    float mean = s * (1.0f / 128.0f);
    float var  = sq * (1.0f / 128.0f) - mean * mean;
    float rstd = rsqrtf(var + 1e-5f);
    float vv[4] = {v.x, v.y, v.z, v.w};
    float ph[8] = {};
#pragma unroll
    for (int e = 0; e < 4; e++) {
        int p = lane * 4 + e;
        float nz = (vv[e] - mean) * rstd * ln_g[p] + ln_b[p];
#pragma unroll
        for (int hh = 0; hh < 8; hh++) ph[hh] += nz * Wpair[p * 8 + hh];
    }
#pragma unroll
    for (int hh = 0; hh < 8; hh++)
#pragma unroll
        for (int o = 16; o; o >>= 1) ph[hh] += __shfl_xor_sync(0xffffffffu, ph[hh], o);
    if (lane == 0)
#pragma unroll
        for (int hh = 0; hh < 8; hh++) g_pbh[(((size_t)hh << 9) + i) * NN + j] = ph[hh];
}

__global__ void attn_softmax_kernel() {
    size_t row = blockIdx.x;
    int t = threadIdx.x;
    size_t off0 = row * 512 + t, off1 = off0 + 256;
    const float scale = 0.17677669529663687f;
    float v0 = (g_dots[off0] + g_dots[off0 + DPL] + g_dots[off0 + 2 * DPL] + g_dots[off0 + 3 * DPL])
               * scale + g_pbh[off0];
    float v1 = (g_dots[off1] + g_dots[off1 + DPL] + g_dots[off1 + 2 * DPL] + g_dots[off1 + 3 * DPL])
               * scale + g_pbh[off1];
    __shared__ float sm[256];
    sm[t] = fmaxf(v0, v1); __syncthreads();
#pragma unroll
    for (int s = 128; s > 0; s >>= 1) { if (t < s) sm[t] = fmaxf(sm[t], sm[t + s]); __syncthreads(); }
    float mx = sm[0]; __syncthreads();
    float e0 = expf(v0 - mx), e1 = expf(v1 - mx);
    sm[t] = e0 + e1; __syncthreads();
#pragma unroll
    for (int s = 128; s > 0; s >>= 1) { if (t < s) sm[t] += sm[t + s]; __syncthreads(); }
    float inv = 1.0f / sm[0];
    g_ph[row * 512 + t]       = __float2half_rn(e0 * inv);
    g_ph[row * 512 + t + 256] = __float2half_rn(e1 * inv);
}

// ============================================================================
extern "C" void kernel_launch(void* const* d_in, const int* in_sizes, int n_in,
                              void* d_out, int out_size) {
    (void)in_sizes; (void)n_in; (void)out_size;
    const float* x         = (const float*)d_in[0];
    const float* pair_bias = (const float*)d_in[1];
    const float* Wq        = (const float*)d_in[2];
    const float* Wkv       = (const float*)d_in[3];
    const float* Wout      = (const float*)d_in[4];
    const float* b_out     = (const float*)d_in[5];
    const float* ln_g      = (const float*)d_in[6];
    const float* ln_b      = (const float*)d_in[7];
    const float* Wpair     = (const float*)d_in[8];
    const float* Wq_sw     = (const float*)d_in[9];
    const float* bq_sw     = (const float*)d_in[10];
    const float* Wk_sw     = (const float*)d_in[11];
    const float* bk_sw     = (const float*)d_in[12];
    float* out = (float*)d_out;

    const int SM128 = 61440;   // 3*(5120+5120)*2
    const int SM256 = 92160;   // 3*(5120+10240)*2
    static int attr_done = 0;
    if (!attr_done) {
        cudaFuncSetAttribute(g16<0, 4, 256>,  cudaFuncAttributeMaxDynamicSharedMemorySize, SM256);
        cudaFuncSetAttribute(g16<1, 32, 256>, cudaFuncAttributeMaxDynamicSharedMemorySize, SM256);
        cudaFuncSetAttribute(g16<2, 16, 256>, cudaFuncAttributeMaxDynamicSharedMemorySize, SM256);
        cudaFuncSetAttribute(g16<3, 8, 128>,  cudaFuncAttributeMaxDynamicSharedMemorySize, SM128);
        cudaFuncSetAttribute(g16<4, 4, 128>,  cudaFuncAttributeMaxDynamicSharedMemorySize, SM128);
        attr_done = 1;
    }

    conv_x             <<<8192, 256>>>(x);
    conv_w             <<<576, 256>>>(Wq, Wkv, Wk_sw, Wout);
    qsw_kernel         <<<NN, 128>>>(x, Wq_sw, bq_sw);
    pbh_kernel         <<<NN * NN / 8, 256>>>(pair_bias, ln_g, ln_b, Wpair);  // 4th: profiled
    g16<4, 4, 128>     <<<dim3(1, 512), 256, SM128>>>(bk_sw, nullptr);        // ksw
    sw_reduce_kernel   <<<MRN, 128>>>();
    wrow_softmax_kernel<<<NN * HH, 128>>>();
    g16<0, 4, 256>     <<<dim3(3, 512), 256, SM256>>>(nullptr, nullptr);      // qkv
    g16<1, 32, 256>    <<<dim3(2, 4, 32), 256, SM256>>>(nullptr, nullptr);    // dots sK=4
    attn_softmax_kernel<<<HH * NN, 256>>>();
    g16<2, 16, 256>    <<<dim3(16, 4, 8), 256, SM256>>>(nullptr, nullptr);    // O
    g16<3, 8, 128>     <<<dim3(1, 512), 256, SM128>>>(b_out, out);            // out
}

// round 11
// speedup vs baseline: 3.2173x; 3.2173x over previous
#include <cuda_runtime.h>
#include <cuda_fp16.h>
#include <cstdint>

#define NN 512
#define HH 8
#define RDC 4096
#define MRN 65536
#define DPL 2097152   // one dots plane
#define STG_H 5120    // halves per smem stage (128*40)
#define SMEM_BYTES 61440

__device__ __align__(16) __half g_xh  [MRN * 128];
__device__ __align__(16) __half g_wt  [896 * 128];
__device__ __align__(16) __half g_woutt[128 * 256];
__device__ __align__(16) __half g_qh  [HH * NN * RDC];
__device__ __align__(16) __half g_kh  [HH * NN * RDC];
__device__ __align__(16) __half g_vh  [HH * NN * RDC];
__device__ __align__(16) __half g_ph  [HH * NN * NN];
__device__ __align__(16) __half g_o2  [MRN * 256];
__device__ __align__(16) float  g_dots[4 * DPL];
__device__ __align__(16) float  g_pbh [HH * NN * NN];
__device__ __align__(16) float  g_ksw [MRN * 128];
__device__ __align__(16) float  g_qsw [NN * 128];
__device__ __align__(16) float  g_wrow[NN * HH * 128];

__device__ __forceinline__ uint32_t smem_u32(const void* p) {
    uint32_t a;
    asm("{ .reg .u64 t; cvta.to.shared.u64 t, %1; cvt.u32.u64 %0, t; }" : "=r"(a) : "l"(p));
    return a;
}
__device__ __forceinline__ void ldm4(uint32_t* r, uint32_t addr) {
    asm volatile("ldmatrix.sync.aligned.m8n8.x4.shared.b16 {%0,%1,%2,%3}, [%4];"
                 : "=r"(r[0]), "=r"(r[1]), "=r"(r[2]), "=r"(r[3]) : "r"(addr));
}
__device__ __forceinline__ void ldm4t(uint32_t* r, uint32_t addr) {
    asm volatile("ldmatrix.sync.aligned.m8n8.x4.trans.shared.b16 {%0,%1,%2,%3}, [%4];"
                 : "=r"(r[0]), "=r"(r[1]), "=r"(r[2]), "=r"(r[3]) : "r"(addr));
}
__device__ __forceinline__ void mma16(float* c, const uint32_t* a, const uint32_t* b) {
    asm volatile("mma.sync.aligned.m16n8k16.row.col.f32.f16.f16.f32 "
        "{%0,%1,%2,%3},{%4,%5,%6,%7},{%8,%9},{%0,%1,%2,%3};"
        : "+f"(c[0]), "+f"(c[1]), "+f"(c[2]), "+f"(c[3])
        : "r"(a[0]), "r"(a[1]), "r"(a[2]), "r"(a[3]), "r"(b[0]), "r"(b[1]));
}
#define CPA16(dst, src) \
    asm volatile("cp.async.cg.shared.global [%0], [%1], 16;" :: "r"(dst), "l"(src) : "memory")

// ============================================================================
// fp16 GEMM (R8-proven): block 128x128, 8 warps (64x32), ktile 32, 3-stage.
// wait -> barrier -> compute(kt) -> issue(kt+2).
// MODE: 0=qkv, 1=dots(split-K=4), 2=O trans-B, 3=out, 4=ksw
// ============================================================================
template<int MODE, int KT>
__global__ __launch_bounds__(256) void g16(const float* __restrict__ auxA,
                                           float* __restrict__ outp) {
    extern __shared__ __half sh[];
    __half* AsB = sh;
    __half* BsB = sh + 3 * STG_H;
    const int t = threadIdx.x, lane = t & 31, warp = t >> 5;
    const int bx = blockIdx.x, by = blockIdx.y;
    const int h = (MODE == 1) ? (blockIdx.z & 7) : blockIdx.z;
    const int split = (MODE == 1) ? (blockIdx.z >> 3) : 0;

    const __half *A, *B; int lda, ldb;
    if (MODE == 0)      { A = g_xh + (size_t)by * 128 * 128; lda = 128;
                          B = g_wt + (size_t)bx * 128 * 128; ldb = 128; }
    else if (MODE == 4) { A = g_xh + (size_t)by * 128 * 128; lda = 128;
                          B = g_wt + (size_t)768 * 128;      ldb = 128; }
    else if (MODE == 1) { A = g_qh + ((size_t)h * 512 + by * 128) * 4096 + split * 1024; lda = 4096;
                          B = g_kh + ((size_t)h * 512 + bx * 128) * 4096 + split * 1024; ldb = 4096; }
    else if (MODE == 2) { A = g_ph + ((size_t)h * 512 + by * 128) * 512; lda = 512;
                          B = g_vh + (size_t)h * 512 * 4096 + bx * 128;  ldb = 4096; }
    else                { A = g_o2 + (size_t)by * 128 * 256; lda = 256;
                          B = g_woutt;                       ldb = 256; }

    auto cpst = [&](int st, int k0) {
        uint32_t da = smem_u32(AsB + st * STG_H), db = smem_u32(BsB + st * STG_H);
#pragma unroll
        for (int c = t; c < 512; c += 256) {
            int row = c >> 2, col = c & 3;
            CPA16(da + row * 80 + col * 16, A + (size_t)row * lda + k0 + col * 8);
        }
        if (MODE == 2) {
#pragma unroll
            for (int c = t; c < 512; c += 256) {
                int row = c >> 4, col = c & 15;
                CPA16(db + row * 272 + col * 16, B + (size_t)(k0 + row) * ldb + col * 8);
            }
        } else {
#pragma unroll
            for (int c = t; c < 512; c += 256) {
                int row = c >> 2, col = c & 3;
                CPA16(db + row * 80 + col * 16, B + (size_t)row * ldb + k0 + col * 8);
            }
        }
        asm volatile("cp.async.commit_group;" ::: "memory");
    };

    float acc[4][4][4] = {};
    const int wm0 = (warp >> 2) * 64, wn0 = (warp & 3) * 32;
    const int q = lane >> 3;

    cpst(0, 0);
    if (KT > 1) cpst(1, 32);
    int st = 0;
    for (int kt = 0; kt < KT; kt++) {
        if (kt + 1 < KT) asm volatile("cp.async.wait_group 1;" ::: "memory");
        else             asm volatile("cp.async.wait_group 0;" ::: "memory");
        __syncthreads();
        uint32_t ab = smem_u32(AsB + st * STG_H), bb = smem_u32(BsB + st * STG_H);
#pragma unroll
        for (int kk = 0; kk < 32; kk += 16) {
            uint32_t af[4][4], bf[2][4];
#pragma unroll
            for (int mt = 0; mt < 4; mt++)
                ldm4(af[mt], ab + (wm0 + mt * 16 + (lane & 15)) * 80 + (kk + (lane >> 4) * 8) * 2);
#pragma unroll
            for (int np = 0; np < 2; np++) {
                if (MODE == 2)
                    ldm4t(bf[np], bb + (kk + (q & 1) * 8 + (lane & 7)) * 272
                                     + (wn0 + np * 16 + (q >> 1) * 8) * 2);
                else
                    ldm4(bf[np], bb + (wn0 + np * 16 + (q >> 1) * 8 + (lane & 7)) * 80
                                    + (kk + (q & 1) * 8) * 2);
            }
#pragma unroll
            for (int mt = 0; mt < 4; mt++)
#pragma unroll
                for (int nt = 0; nt < 4; nt++)
                    mma16(acc[mt][nt], af[mt], &bf[nt >> 1][(nt & 1) * 2]);
        }
        if (kt + 2 < KT) {
            int ns = st + 2; if (ns >= 3) ns -= 3;
            cpst(ns, (kt + 2) * 32);
        }
        st = (st == 2) ? 0 : st + 1;
    }

#pragma unroll
    for (int mt = 0; mt < 4; mt++)
#pragma unroll
        for (int nt = 0; nt < 4; nt++)
#pragma unroll
            for (int hf = 0; hf < 2; hf++) {
                int mrow = wm0 + mt * 16 + (lane >> 2) + hf * 8;
                int ncol = wn0 + nt * 8 + (lane & 3) * 2;
                float v0 = acc[mt][nt][hf * 2], v1 = acc[mt][nt][hf * 2 + 1];
                if (MODE == 0) {
                    int m = by * 128 + mrow, c = bx * 128 + ncol;
                    int r = m >> 9, n = m & 511;
                    if (c < 256) {
                        int hh = c >> 5, d = c & 31;
                        float w = g_wrow[(n * 8 + hh) * 128 + r];
                        *reinterpret_cast<__half2*>(
                            &g_qh[((size_t)(hh * 512 + n)) * 4096 + r * 32 + d]) =
                            __floats2half2_rn(v0 * w, v1 * w);
                    } else if (c < 512) {
                        int cc = c - 256, hh = cc >> 5, d = cc & 31;
                        *reinterpret_cast<__half2*>(
                            &g_kh[((size_t)(hh * 512 + n)) * 4096 + r * 32 + d]) =
                            __floats2half2_rn(v0, v1);
                    } else {
                        int cc = c - 512, hh = cc >> 5, d = cc & 31;
                        *reinterpret_cast<__half2*>(
                            &g_vh[((size_t)(hh * 512 + n)) * 4096 + r * 32 + d]) =
                            __floats2half2_rn(v0, v1);
                    }
                } else if (MODE == 4) {
                    int m = by * 128 + mrow;
                    g_ksw[(size_t)m * 128 + ncol]     = v0 + auxA[ncol];
                    g_ksw[(size_t)m * 128 + ncol + 1] = v1 + auxA[ncol + 1];
                } else if (MODE == 1) {
                    int i = by * 128 + mrow, j = bx * 128 + ncol;
                    size_t off = (size_t)split * DPL + ((size_t)h * 512 + i) * 512 + j;
                    g_dots[off]     = v0;
                    g_dots[off + 1] = v1;
                } else if (MODE == 2) {
                    int i = by * 128 + mrow, tcol = bx * 128 + ncol;
                    int r = tcol >> 5, d = tcol & 31;
                    *reinterpret_cast<__half2*>(
                        &g_o2[((size_t)r * 512 + i) * 256 + h * 32 + d]) =
                        __floats2half2_rn(v0, v1);
                } else {
                    int m = by * 128 + mrow;
                    outp[(size_t)m * 128 + ncol]     = v0 + auxA[ncol];
                    outp[(size_t)m * 128 + ncol + 1] = v1 + auxA[ncol + 1];
                }
            }
}

// ============================================================================
// pbh: LN(pair_bias) @ Wpair, warp-per-row grid-stride; Wpair/LN in registers.
// ============================================================================
__global__ __launch_bounds__(256) void pbh_kernel(const float* __restrict__ pair_bias,
                                                  const float* __restrict__ ln_g,
                                                  const float* __restrict__ ln_b,
                                                  const float* __restrict__ Wpair) {
    const int lane = threadIdx.x & 31;
    const int gw = (blockIdx.x * 256 + threadIdx.x) >> 5;
    const int nw = (gridDim.x * 256) >> 5;
    const int p0 = lane * 4;

    // per-lane constants: 4 LN rows + 4x8 Wpair rows
    float gg[4], bb[4], wp[4][8];
#pragma unroll
    for (int e = 0; e < 4; e++) {
        gg[e] = ln_g[p0 + e];
        bb[e] = ln_b[p0 + e];
        float4 w0 = *reinterpret_cast<const float4*>(&Wpair[(p0 + e) * 8]);
        float4 w1 = *reinterpret_cast<const float4*>(&Wpair[(p0 + e) * 8 + 4]);
        wp[e][0] = w0.x; wp[e][1] = w0.y; wp[e][2] = w0.z; wp[e][3] = w0.w;
        wp[e][4] = w1.x; wp[e][5] = w1.y; wp[e][6] = w1.z; wp[e][7] = w1.w;
    }

    for (int idx = gw; idx < NN * NN; idx += nw) {
        int i = idx >> 9, j = idx & 511;
        float4 v = *reinterpret_cast<const float4*>(&pair_bias[(size_t)idx * 128 + p0]);
        float s  = v.x + v.y + v.z + v.w;
        float sq = v.x * v.x + v.y * v.y + v.z * v.z + v.w * v.w;
#pragma unroll
        for (int o = 16; o; o >>= 1) {
            s  += __shfl_xor_sync(0xffffffffu, s, o);
            sq += __shfl_xor_sync(0xffffffffu, sq, o);
        }
        float mean = s * (1.0f / 128.0f);
        float var  = sq * (1.0f / 128.0f) - mean * mean;
        float rstd = rsqrtf(var + 1e-5f);
        float vv[4] = {v.x, v.y, v.z, v.w};
        float ph[8] = {};
#pragma unroll
        for (int e = 0; e < 4; e++) {
            float nz = (vv[e] - mean) * rstd * gg[e] + bb[e];
#pragma unroll
            for (int hh = 0; hh < 8; hh++) ph[hh] += nz * wp[e][hh];
        }
#pragma unroll
        for (int hh = 0; hh < 8; hh++)
#pragma unroll
            for (int o = 16; o; o >>= 1) ph[hh] += __shfl_xor_sync(0xffffffffu, ph[hh], o);
        // after butterfly all lanes hold full sums; lanes 0-7 write heads 0-7
        float outv = ph[0];
#pragma unroll
        for (int hh = 1; hh < 8; hh++) if (lane == hh) outv = ph[hh];
        if (lane < 8)
            g_pbh[(((size_t)lane << 9) + i) * NN + j] = outv;
    }
}

// ============================================================================
__global__ void conv_x(const float* __restrict__ x) {
    size_t i = ((size_t)blockIdx.x * 256 + threadIdx.x) * 4;
    float4 v = *reinterpret_cast<const float4*>(x + i);
    __half2* d = reinterpret_cast<__half2*>(&g_xh[i]);
    d[0] = __floats2half2_rn(v.x, v.y);
    d[1] = __floats2half2_rn(v.z, v.w);
}

__global__ void conv_w(const float* __restrict__ Wq, const float* __restrict__ Wkv,
                       const float* __restrict__ Wk_sw, const float* __restrict__ Wout) {
    int g = blockIdx.x * 256 + threadIdx.x;
    if (g < 114688) {
        int row = g >> 7, k = g & 127;
        float v;
        if (row < 256)      v = Wq[k * 256 + row];
        else if (row < 768) v = Wkv[k * 512 + (row - 256)];
        else                v = Wk_sw[k * 128 + (row - 768)];
        g_wt[g] = __float2half_rn(v);
    } else {
        int g2 = g - 114688;
        int c = g2 >> 8, k = g2 & 255;
        g_woutt[g2] = __float2half_rn(Wout[k * 128 + c]);
    }
}

__global__ void qsw_kernel(const float* __restrict__ x, const float* __restrict__ Wq_sw,
                           const float* __restrict__ bq_sw) {
    int n = blockIdx.x, c = threadIdx.x;
    __shared__ float xr[128];
    xr[c] = x[(size_t)n * 128 + c];
    __syncthreads();
    float acc = bq_sw[c];
#pragma unroll 8
    for (int k = 0; k < 128; k++) acc += xr[k] * Wq_sw[k * 128 + c];
    g_qsw[n * 128 + c] = acc;
}

__global__ void sw_reduce_kernel() {
    int m = blockIdx.x, r = m >> 9, n = m & 511, c = threadIdx.x;
    float prod = g_ksw[(size_t)m * 128 + c] * g_qsw[n * 128 + c];
#pragma unroll
    for (int o = 8; o; o >>= 1) prod += __shfl_down_sync(0xffffffffu, prod, o, 16);
    if ((c & 15) == 0) g_wrow[(n * 8 + (c >> 4)) * 128 + r] = prod * 0.25f;
}

__global__ void wrow_softmax_kernel() {
    int row = blockIdx.x, t = threadIdx.x;
    float v = g_wrow[(size_t)row * 128 + t];
    __shared__ float sm[128];
    sm[t] = v; __syncthreads();
#pragma unroll
    for (int s = 64; s > 0; s >>= 1) { if (t < s) sm[t] = fmaxf(sm[t], sm[t + s]); __syncthreads(); }
    float mx = sm[0]; __syncthreads();
    float e = expf(v - mx);
    sm[t] = e; __syncthreads();
#pragma unroll
    for (int s = 64; s > 0; s >>= 1) { if (t < s) sm[t] += sm[t + s]; __syncthreads(); }
    g_wrow[(size_t)row * 128 + t] = e / sm[0];
}

__global__ void attn_softmax_kernel() {
    size_t row = blockIdx.x;
    int t = threadIdx.x;
    size_t off0 = row * 512 + t, off1 = off0 + 256;
    const float scale = 0.17677669529663687f;
    float v0 = (g_dots[off0] + g_dots[off0 + DPL] + g_dots[off0 + 2 * DPL] + g_dots[off0 + 3 * DPL])
               * scale + g_pbh[off0];
    float v1 = (g_dots[off1] + g_dots[off1 + DPL] + g_dots[off1 + 2 * DPL] + g_dots[off1 + 3 * DPL])
               * scale + g_pbh[off1];
    __shared__ float sm[256];
    sm[t] = fmaxf(v0, v1); __syncthreads();
#pragma unroll
    for (int s = 128; s > 0; s >>= 1) { if (t < s) sm[t] = fmaxf(sm[t], sm[t + s]); __syncthreads(); }
    float mx = sm[0]; __syncthreads();
    float e0 = expf(v0 - mx), e1 = expf(v1 - mx);
    sm[t] = e0 + e1; __syncthreads();
#pragma unroll
    for (int s = 128; s > 0; s >>= 1) { if (t < s) sm[t] += sm[t + s]; __syncthreads(); }
    float inv = 1.0f / sm[0];
    g_ph[row * 512 + t]       = __float2half_rn(e0 * inv);
    g_ph[row * 512 + t + 256] = __float2half_rn(e1 * inv);
}

// ============================================================================
extern "C" void kernel_launch(void* const* d_in, const int* in_sizes, int n_in,
                              void* d_out, int out_size) {
    (void)in_sizes; (void)n_in; (void)out_size;
    const float* x         = (const float*)d_in[0];
    const float* pair_bias = (const float*)d_in[1];
    const float* Wq        = (const float*)d_in[2];
    const float* Wkv       = (const float*)d_in[3];
    const float* Wout      = (const float*)d_in[4];
    const float* b_out     = (const float*)d_in[5];
    const float* ln_g      = (const float*)d_in[6];
    const float* ln_b      = (const float*)d_in[7];
    const float* Wpair     = (const float*)d_in[8];
    const float* Wq_sw     = (const float*)d_in[9];
    const float* bq_sw     = (const float*)d_in[10];
    const float* Wk_sw     = (const float*)d_in[11];
    const float* bk_sw     = (const float*)d_in[12];
    float* out = (float*)d_out;

    static int attr_done = 0;
    if (!attr_done) {
        cudaFuncSetAttribute(g16<0, 4>,  cudaFuncAttributeMaxDynamicSharedMemorySize, SMEM_BYTES);
        cudaFuncSetAttribute(g16<1, 32>, cudaFuncAttributeMaxDynamicSharedMemorySize, SMEM_BYTES);
        cudaFuncSetAttribute(g16<2, 16>, cudaFuncAttributeMaxDynamicSharedMemorySize, SMEM_BYTES);
        cudaFuncSetAttribute(g16<3, 8>,  cudaFuncAttributeMaxDynamicSharedMemorySize, SMEM_BYTES);
        cudaFuncSetAttribute(g16<4, 4>,  cudaFuncAttributeMaxDynamicSharedMemorySize, SMEM_BYTES);
        attr_done = 1;
    }

    conv_x             <<<8192, 256>>>(x);
    conv_w             <<<576, 256>>>(Wq, Wkv, Wk_sw, Wout);
    qsw_kernel         <<<NN, 128>>>(x, Wq_sw, bq_sw);
    pbh_kernel         <<<2048, 256>>>(pair_bias, ln_g, ln_b, Wpair);        // 4th: profiled
    g16<4, 4>          <<<dim3(1, 512), 256, SMEM_BYTES>>>(bk_sw, nullptr);  // ksw
    sw_reduce_kernel   <<<MRN, 128>>>();
    wrow_softmax_kernel<<<NN * HH, 128>>>();
    g16<0, 4>          <<<dim3(6, 512), 256, SMEM_BYTES>>>(nullptr, nullptr);   // qkv
    g16<1, 32>         <<<dim3(4, 4, 32), 256, SMEM_BYTES>>>(nullptr, nullptr); // dots sK=4
    attn_softmax_kernel<<<HH * NN, 256>>>();
    g16<2, 16>         <<<dim3(32, 4, 8), 256, SMEM_BYTES>>>(nullptr, nullptr); // O
    g16<3, 8>          <<<dim3(1, 512), 256, SMEM_BYTES>>>(b_out, out);         // out
}

// round 12
// speedup vs baseline: 3.4830x; 1.0826x over previous
#include <cuda_runtime.h>
#include <cuda_fp16.h>
#include <cstdint>

#define NN 512
#define HH 8
#define RDC 4096
#define MRN 65536
#define DPL 2097152    // one dots plane
#define ASTG_H 9216    // halves per smem stage (128 rows * 144B)
#define SMEM_BYTES 110592

__device__ __align__(16) __half g_xh  [MRN * 128];
__device__ __align__(16) __half g_wt  [896 * 128];
__device__ __align__(16) __half g_woutt[128 * 256];
__device__ __align__(16) __half g_qh  [HH * NN * RDC];
__device__ __align__(16) __half g_kh  [HH * NN * RDC];
__device__ __align__(16) __half g_vh  [HH * NN * RDC];
__device__ __align__(16) __half g_ph  [HH * NN * NN];
__device__ __align__(16) __half g_o2  [MRN * 256];
__device__ __align__(16) float  g_dots[4 * DPL];
__device__ __align__(16) float  g_pbh [HH * NN * NN];
__device__ __align__(16) float  g_ksw [MRN * 128];
__device__ __align__(16) float  g_qsw [NN * 128];
__device__ __align__(16) float  g_wrow[NN * HH * 128];

__device__ __forceinline__ uint32_t smem_u32(const void* p) {
    uint32_t a;
    asm("{ .reg .u64 t; cvta.to.shared.u64 t, %1; cvt.u32.u64 %0, t; }" : "=r"(a) : "l"(p));
    return a;
}
__device__ __forceinline__ void ldm4(uint32_t* r, uint32_t addr) {
    asm volatile("ldmatrix.sync.aligned.m8n8.x4.shared.b16 {%0,%1,%2,%3}, [%4];"
                 : "=r"(r[0]), "=r"(r[1]), "=r"(r[2]), "=r"(r[3]) : "r"(addr));
}
__device__ __forceinline__ void ldm4t(uint32_t* r, uint32_t addr) {
    asm volatile("ldmatrix.sync.aligned.m8n8.x4.trans.shared.b16 {%0,%1,%2,%3}, [%4];"
                 : "=r"(r[0]), "=r"(r[1]), "=r"(r[2]), "=r"(r[3]) : "r"(addr));
}
__device__ __forceinline__ void mma16(float* c, const uint32_t* a, const uint32_t* b) {
    asm volatile("mma.sync.aligned.m16n8k16.row.col.f32.f16.f16.f32 "
        "{%0,%1,%2,%3},{%4,%5,%6,%7},{%8,%9},{%0,%1,%2,%3};"
        : "+f"(c[0]), "+f"(c[1]), "+f"(c[2]), "+f"(c[3])
        : "r"(a[0]), "r"(a[1]), "r"(a[2]), "r"(a[3]), "r"(b[0]), "r"(b[1]));
}
#define CPA16(dst, src) \
    asm volatile("cp.async.cg.shared.global [%0], [%1], 16;" :: "r"(dst), "l"(src) : "memory")

// ============================================================================
// fp16 GEMM: block 128x128, 8 warps (64x32), ktile 64, 3-stage, 1 sync/ktile.
// wait -> barrier -> compute(kt) -> issue(kt+2).   KT = K/64.
// MODE: 0=qkv, 1=dots(split-K=4), 2=O trans-B, 3=out, 4=ksw
// ============================================================================
template<int MODE, int KT>
__global__ __launch_bounds__(256) void g16(const float* __restrict__ auxA,
                                           float* __restrict__ outp) {
    extern __shared__ __half sh[];
    __half* AsB = sh;
    __half* BsB = sh + 3 * ASTG_H;
    const int t = threadIdx.x, lane = t & 31, warp = t >> 5;
    const int bx = blockIdx.x, by = blockIdx.y;
    const int h = (MODE == 1) ? (blockIdx.z & 7) : blockIdx.z;
    const int split = (MODE == 1) ? (blockIdx.z >> 3) : 0;

    const __half *A, *B; int lda, ldb;
    if (MODE == 0)      { A = g_xh + (size_t)by * 128 * 128; lda = 128;
                          B = g_wt + (size_t)bx * 128 * 128; ldb = 128; }
    else if (MODE == 4) { A = g_xh + (size_t)by * 128 * 128; lda = 128;
                          B = g_wt + (size_t)768 * 128;      ldb = 128; }
    else if (MODE == 1) { A = g_qh + ((size_t)h * 512 + by * 128) * 4096 + split * 1024; lda = 4096;
                          B = g_kh + ((size_t)h * 512 + bx * 128) * 4096 + split * 1024; ldb = 4096; }
    else if (MODE == 2) { A = g_ph + ((size_t)h * 512 + by * 128) * 512; lda = 512;
                          B = g_vh + (size_t)h * 512 * 4096 + bx * 128;  ldb = 4096; }
    else                { A = g_o2 + (size_t)by * 128 * 256; lda = 256;
                          B = g_woutt;                       ldb = 256; }

    // one stage = A[128 rows][64 k] stride 144B  +  B same (trans: [64 k][128 n] stride 272B)
    auto cpst = [&](int st, int k0) {
        uint32_t da = smem_u32(AsB + st * ASTG_H), db = smem_u32(BsB + st * ASTG_H);
#pragma unroll
        for (int c = t; c < 1024; c += 256) {
            int row = c >> 3, col = c & 7;
            CPA16(da + row * 144 + col * 16, A + (size_t)row * lda + k0 + col * 8);
        }
        if (MODE == 2) {
#pragma unroll
            for (int c = t; c < 1024; c += 256) {
                int row = c >> 4, col = c & 15;
                CPA16(db + row * 272 + col * 16, B + (size_t)(k0 + row) * ldb + col * 8);
            }
        } else {
#pragma unroll
            for (int c = t; c < 1024; c += 256) {
                int row = c >> 3, col = c & 7;
                CPA16(db + row * 144 + col * 16, B + (size_t)row * ldb + k0 + col * 8);
            }
        }
        asm volatile("cp.async.commit_group;" ::: "memory");
    };

    float acc[4][4][4] = {};
    const int wm0 = (warp >> 2) * 64, wn0 = (warp & 3) * 32;
    const int q = lane >> 3;

    cpst(0, 0);
    if (KT > 1) cpst(1, 64);
    int st = 0;
    for (int kt = 0; kt < KT; kt++) {
        if (kt + 1 < KT) asm volatile("cp.async.wait_group 1;" ::: "memory");
        else             asm volatile("cp.async.wait_group 0;" ::: "memory");
        __syncthreads();
        uint32_t ab = smem_u32(AsB + st * ASTG_H), bb = smem_u32(BsB + st * ASTG_H);
#pragma unroll
        for (int kk = 0; kk < 64; kk += 16) {
            uint32_t af[4][4], bf[2][4];
#pragma unroll
            for (int mt = 0; mt < 4; mt++)
                ldm4(af[mt], ab + (wm0 + mt * 16 + (lane & 15)) * 144 + (kk + (lane >> 4) * 8) * 2);
#pragma unroll
            for (int np = 0; np < 2; np++) {
                if (MODE == 2)
                    ldm4t(bf[np], bb + (kk + (q & 1) * 8 + (lane & 7)) * 272
                                     + (wn0 + np * 16 + (q >> 1) * 8) * 2);
                else
                    ldm4(bf[np], bb + (wn0 + np * 16 + (q >> 1) * 8 + (lane & 7)) * 144
                                    + (kk + (q & 1) * 8) * 2);
            }
#pragma unroll
            for (int mt = 0; mt < 4; mt++)
#pragma unroll
                for (int nt = 0; nt < 4; nt++)
                    mma16(acc[mt][nt], af[mt], &bf[nt >> 1][(nt & 1) * 2]);
        }
        if (kt + 2 < KT) {
            int ns = st + 2; if (ns >= 3) ns -= 3;
            cpst(ns, (kt + 2) * 64);
        }
        st = (st == 2) ? 0 : st + 1;
    }

#pragma unroll
    for (int mt = 0; mt < 4; mt++)
#pragma unroll
        for (int nt = 0; nt < 4; nt++)
#pragma unroll
            for (int hf = 0; hf < 2; hf++) {
                int mrow = wm0 + mt * 16 + (lane >> 2) + hf * 8;
                int ncol = wn0 + nt * 8 + (lane & 3) * 2;
                float v0 = acc[mt][nt][hf * 2], v1 = acc[mt][nt][hf * 2 + 1];
                if (MODE == 0) {
                    int m = by * 128 + mrow, c = bx * 128 + ncol;
                    int r = m >> 9, n = m & 511;
                    if (c < 256) {
                        int hh = c >> 5, d = c & 31;
                        float w = g_wrow[(n * 8 + hh) * 128 + r];
                        *reinterpret_cast<__half2*>(
                            &g_qh[((size_t)(hh * 512 + n)) * 4096 + r * 32 + d]) =
                            __floats2half2_rn(v0 * w, v1 * w);
                    } else if (c < 512) {
                        int cc = c - 256, hh = cc >> 5, d = cc & 31;
                        *reinterpret_cast<__half2*>(
                            &g_kh[((size_t)(hh * 512 + n)) * 4096 + r * 32 + d]) =
                            __floats2half2_rn(v0, v1);
                    } else {
                        int cc = c - 512, hh = cc >> 5, d = cc & 31;
                        *reinterpret_cast<__half2*>(
                            &g_vh[((size_t)(hh * 512 + n)) * 4096 + r * 32 + d]) =
                            __floats2half2_rn(v0, v1);
                    }
                } else if (MODE == 4) {
                    int m = by * 128 + mrow;
                    g_ksw[(size_t)m * 128 + ncol]     = v0 + auxA[ncol];
                    g_ksw[(size_t)m * 128 + ncol + 1] = v1 + auxA[ncol + 1];
                } else if (MODE == 1) {
                    int i = by * 128 + mrow, j = bx * 128 + ncol;
                    size_t off = (size_t)split * DPL + ((size_t)h * 512 + i) * 512 + j;
                    g_dots[off]     = v0;
                    g_dots[off + 1] = v1;
                } else if (MODE == 2) {
                    int i = by * 128 + mrow, tcol = bx * 128 + ncol;
                    int r = tcol >> 5, d = tcol & 31;
                    *reinterpret_cast<__half2*>(
                        &g_o2[((size_t)r * 512 + i) * 256 + h * 32 + d]) =
                        __floats2half2_rn(v0, v1);
                } else {
                    int m = by * 128 + mrow;
                    outp[(size_t)m * 128 + ncol]     = v0 + auxA[ncol];
                    outp[(size_t)m * 128 + ncol + 1] = v1 + auxA[ncol + 1];
                }
            }
}

// ============================================================================
// pbh: LN(pair_bias) @ Wpair.  Warp per row, 2 rows/iter, split-tree head
// reduction (16 shuffles instead of 40).
// ============================================================================
__global__ __launch_bounds__(256) void pbh_kernel(const float* __restrict__ pair_bias,
                                                  const float* __restrict__ ln_g,
                                                  const float* __restrict__ ln_b,
                                                  const float* __restrict__ Wpair) {
    const int lane = threadIdx.x & 31;
    const int gw = (blockIdx.x * 256 + threadIdx.x) >> 5;
    const int nw = (gridDim.x * 256) >> 5;
    const int p0 = lane * 4;

    float gg[4], bb4[4], wp[4][8];
#pragma unroll
    for (int e = 0; e < 4; e++) {
        gg[e]  = ln_g[p0 + e];
        bb4[e] = ln_b[p0 + e];
        float4 w0 = *reinterpret_cast<const float4*>(&Wpair[(p0 + e) * 8]);
        float4 w1 = *reinterpret_cast<const float4*>(&Wpair[(p0 + e) * 8 + 4]);
        wp[e][0] = w0.x; wp[e][1] = w0.y; wp[e][2] = w0.z; wp[e][3] = w0.w;
        wp[e][4] = w1.x; wp[e][5] = w1.y; wp[e][6] = w1.z; wp[e][7] = w1.w;
    }
    // head this lane ends up holding after the split-tree
    const int myh = ((lane >> 4) & 1) * 4 + ((lane >> 3) & 1) * 2 + ((lane >> 2) & 1);
    const bool writer = (lane & 3) == 0;

    for (int idx = gw * 2; idx < NN * NN; idx += nw * 2) {
        float4 va = *reinterpret_cast<const float4*>(&pair_bias[(size_t)idx * 128 + p0]);
        float4 vb = *reinterpret_cast<const float4*>(&pair_bias[(size_t)(idx + 1) * 128 + p0]);
        float vv[2][4] = {{va.x, va.y, va.z, va.w}, {vb.x, vb.y, vb.z, vb.w}};
        float s[2], sq[2];
#pragma unroll
        for (int rr = 0; rr < 2; rr++) {
            s[rr]  = vv[rr][0] + vv[rr][1] + vv[rr][2] + vv[rr][3];
            sq[rr] = vv[rr][0] * vv[rr][0] + vv[rr][1] * vv[rr][1]
                   + vv[rr][2] * vv[rr][2] + vv[rr][3] * vv[rr][3];
        }
#pragma unroll
        for (int o = 16; o; o >>= 1) {
#pragma unroll
            for (int rr = 0; rr < 2; rr++) {
                s[rr]  += __shfl_xor_sync(0xffffffffu, s[rr], o);
                sq[rr] += __shfl_xor_sync(0xffffffffu, sq[rr], o);
            }
        }
        float ph[2][8] = {};
#pragma unroll
        for (int rr = 0; rr < 2; rr++) {
            float mean = s[rr] * (1.0f / 128.0f);
            float var  = sq[rr] * (1.0f / 128.0f) - mean * mean;
            float rstd = rsqrtf(var + 1e-5f);
#pragma unroll
            for (int e = 0; e < 4; e++) {
                float nz = (vv[rr][e] - mean) * rstd * gg[e] + bb4[e];
#pragma unroll
                for (int hh = 0; hh < 8; hh++) ph[rr][hh] += nz * wp[e][hh];
            }
        }
        // split-tree reduce: 8 -> 4 -> 2 -> 1 live values (16 shuffles/row)
#pragma unroll
        for (int rr = 0; rr < 2; rr++) {
            float* v = ph[rr];
#pragma unroll
            for (int hh = 0; hh < 8; hh++) v[hh] += __shfl_xor_sync(0xffffffffu, v[hh], 16);
            if (lane & 16) { v[0] = v[4]; v[1] = v[5]; v[2] = v[6]; v[3] = v[7]; }
#pragma unroll
            for (int hh = 0; hh < 4; hh++) v[hh] += __shfl_xor_sync(0xffffffffu, v[hh], 8);
            if (lane & 8) { v[0] = v[2]; v[1] = v[3]; }
#pragma unroll
            for (int hh = 0; hh < 2; hh++) v[hh] += __shfl_xor_sync(0xffffffffu, v[hh], 4);
            if (lane & 4) { v[0] = v[1]; }
            v[0] += __shfl_xor_sync(0xffffffffu, v[0], 2);
            v[0] += __shfl_xor_sync(0xffffffffu, v[0], 1);
        }
        if (writer) {
            int i0 = idx >> 9, j0 = idx & 511;
            int i1 = (idx + 1) >> 9, j1 = (idx + 1) & 511;
            g_pbh[(((size_t)myh << 9) + i0) * NN + j0] = ph[0][0];
            g_pbh[(((size_t)myh << 9) + i1) * NN + j1] = ph[1][0];
        }
    }
}

// ============================================================================
__global__ void conv_x(const float* __restrict__ x) {
    size_t i = ((size_t)blockIdx.x * 256 + threadIdx.x) * 4;
    float4 v = *reinterpret_cast<const float4*>(x + i);
    __half2* d = reinterpret_cast<__half2*>(&g_xh[i]);
    d[0] = __floats2half2_rn(v.x, v.y);
    d[1] = __floats2half2_rn(v.z, v.w);
}

__global__ void conv_w(const float* __restrict__ Wq, const float* __restrict__ Wkv,
                       const float* __restrict__ Wk_sw, const float* __restrict__ Wout) {
    int g = blockIdx.x * 256 + threadIdx.x;
    if (g < 114688) {
        int row = g >> 7, k = g & 127;
        float v;
        if (row < 256)      v = Wq[k * 256 + row];
        else if (row < 768) v = Wkv[k * 512 + (row - 256)];
        else                v = Wk_sw[k * 128 + (row - 768)];
        g_wt[g] = __float2half_rn(v);
    } else {
        int g2 = g - 114688;
        int c = g2 >> 8, k = g2 & 255;
        g_woutt[g2] = __float2half_rn(Wout[k * 128 + c]);
    }
}

__global__ void qsw_kernel(const float* __restrict__ x, const float* __restrict__ Wq_sw,
                           const float* __restrict__ bq_sw) {
    int n = blockIdx.x, c = threadIdx.x;
    __shared__ float xr[128];
    xr[c] = x[(size_t)n * 128 + c];
    __syncthreads();
    float acc = bq_sw[c];
#pragma unroll 8
    for (int k = 0; k < 128; k++) acc += xr[k] * Wq_sw[k * 128 + c];
    g_qsw[n * 128 + c] = acc;
}

__global__ void sw_reduce_kernel() {
    int m = blockIdx.x, r = m >> 9, n = m & 511, c = threadIdx.x;
    float prod = g_ksw[(size_t)m * 128 + c] * g_qsw[n * 128 + c];
#pragma unroll
    for (int o = 8; o; o >>= 1) prod += __shfl_down_sync(0xffffffffu, prod, o, 16);
    if ((c & 15) == 0) g_wrow[(n * 8 + (c >> 4)) * 128 + r] = prod * 0.25f;
}

__global__ void wrow_softmax_kernel() {
    int row = blockIdx.x, t = threadIdx.x;
    float v = g_wrow[(size_t)row * 128 + t];
    __shared__ float sm[128];
    sm[t] = v; __syncthreads();
#pragma unroll
    for (int s = 64; s > 0; s >>= 1) { if (t < s) sm[t] = fmaxf(sm[t], sm[t + s]); __syncthreads(); }
    float mx = sm[0]; __syncthreads();
    float e = expf(v - mx);
    sm[t] = e; __syncthreads();
#pragma unroll
    for (int s = 64; s > 0; s >>= 1) { if (t < s) sm[t] += sm[t + s]; __syncthreads(); }
    g_wrow[(size_t)row * 128 + t] = e / sm[0];
}

__global__ void attn_softmax_kernel() {
    size_t row = blockIdx.x;
    int t = threadIdx.x;
    size_t off0 = row * 512 + t, off1 = off0 + 256;
    const float scale = 0.17677669529663687f;
    float v0 = (g_dots[off0] + g_dots[off0 + DPL] + g_dots[off0 + 2 * DPL] + g_dots[off0 + 3 * DPL])
               * scale + g_pbh[off0];
    float v1 = (g_dots[off1] + g_dots[off1 + DPL] + g_dots[off1 + 2 * DPL] + g_dots[off1 + 3 * DPL])
               * scale + g_pbh[off1];
    __shared__ float sm[256];
    sm[t] = fmaxf(v0, v1); __syncthreads();
#pragma unroll
    for (int s = 128; s > 0; s >>= 1) { if (t < s) sm[t] = fmaxf(sm[t], sm[t + s]); __syncthreads(); }
    float mx = sm[0]; __syncthreads();
    float e0 = expf(v0 - mx), e1 = expf(v1 - mx);
    sm[t] = e0 + e1; __syncthreads();
#pragma unroll
    for (int s = 128; s > 0; s >>= 1) { if (t < s) sm[t] += sm[t + s]; __syncthreads(); }
    float inv = 1.0f / sm[0];
    g_ph[row * 512 + t]       = __float2half_rn(e0 * inv);
    g_ph[row * 512 + t + 256] = __float2half_rn(e1 * inv);
}

// ============================================================================
extern "C" void kernel_launch(void* const* d_in, const int* in_sizes, int n_in,
                              void* d_out, int out_size) {
    (void)in_sizes; (void)n_in; (void)out_size;
    const float* x         = (const float*)d_in[0];
    const float* pair_bias = (const float*)d_in[1];
    const float* Wq        = (const float*)d_in[2];
    const float* Wkv       = (const float*)d_in[3];
    const float* Wout      = (const float*)d_in[4];
    const float* b_out     = (const float*)d_in[5];
    const float* ln_g      = (const float*)d_in[6];
    const float* ln_b      = (const float*)d_in[7];
    const float* Wpair     = (const float*)d_in[8];
    const float* Wq_sw     = (const float*)d_in[9];
    const float* bq_sw     = (const float*)d_in[10];
    const float* Wk_sw     = (const float*)d_in[11];
    const float* bk_sw     = (const float*)d_in[12];
    float* out = (float*)d_out;

    static int attr_done = 0;
    if (!attr_done) {
        cudaFuncSetAttribute(g16<0, 2>,  cudaFuncAttributeMaxDynamicSharedMemorySize, SMEM_BYTES);
        cudaFuncSetAttribute(g16<1, 16>, cudaFuncAttributeMaxDynamicSharedMemorySize, SMEM_BYTES);
        cudaFuncSetAttribute(g16<2, 8>,  cudaFuncAttributeMaxDynamicSharedMemorySize, SMEM_BYTES);
        cudaFuncSetAttribute(g16<3, 4>,  cudaFuncAttributeMaxDynamicSharedMemorySize, SMEM_BYTES);
        cudaFuncSetAttribute(g16<4, 2>,  cudaFuncAttributeMaxDynamicSharedMemorySize, SMEM_BYTES);
        attr_done = 1;
    }

    conv_x             <<<8192, 256>>>(x);
    conv_w             <<<576, 256>>>(Wq, Wkv, Wk_sw, Wout);
    qsw_kernel         <<<NN, 128>>>(x, Wq_sw, bq_sw);
    pbh_kernel         <<<2048, 256>>>(pair_bias, ln_g, ln_b, Wpair);        // 4th: profiled
    g16<4, 2>          <<<dim3(1, 512), 256, SMEM_BYTES>>>(bk_sw, nullptr);  // ksw
    sw_reduce_kernel   <<<MRN, 128>>>();
    wrow_softmax_kernel<<<NN * HH, 128>>>();
    g16<0, 2>          <<<dim3(6, 512), 256, SMEM_BYTES>>>(nullptr, nullptr);   // qkv
    g16<1, 16>         <<<dim3(4, 4, 32), 256, SMEM_BYTES>>>(nullptr, nullptr); // dots sK=4
    attn_softmax_kernel<<<HH * NN, 256>>>();
    g16<2, 8>          <<<dim3(32, 4, 8), 256, SMEM_BYTES>>>(nullptr, nullptr); // O
    g16<3, 4>          <<<dim3(1, 512), 256, SMEM_BYTES>>>(b_out, out);         // out
}

// round 13
// speedup vs baseline: 3.8601x; 1.1083x over previous
#include <cuda_runtime.h>
#include <cuda_fp16.h>
#include <cstdint>

#define NN 512
#define HH 8
#define RDC 4096
#define MRN 65536
#define DPL 2097152    // one dots plane
#define ASTG_H 9216    // halves per smem stage (128 rows * 144B)
#define SMEM_BYTES 110592

__device__ __align__(16) __half g_xh  [MRN * 128];
__device__ __align__(16) __half g_wt  [896 * 128];
__device__ __align__(16) __half g_woutt[128 * 256];
__device__ __align__(16) __half g_qh  [HH * NN * RDC];
__device__ __align__(16) __half g_kh  [HH * NN * RDC];
__device__ __align__(16) __half g_vh  [HH * NN * RDC];
__device__ __align__(16) __half g_ph  [HH * NN * NN];
__device__ __align__(16) __half g_o2  [MRN * 256];
__device__ __align__(16) float  g_dots[2 * DPL];
__device__ __align__(16) float  g_pbh [HH * NN * NN];
__device__ __align__(16) float  g_qsw [NN * 128];
__device__ __align__(16) float  g_wrow[NN * HH * 128];

__device__ __forceinline__ uint32_t smem_u32(const void* p) {
    uint32_t a;
    asm("{ .reg .u64 t; cvta.to.shared.u64 t, %1; cvt.u32.u64 %0, t; }" : "=r"(a) : "l"(p));
    return a;
}
__device__ __forceinline__ void ldm4(uint32_t* r, uint32_t addr) {
    asm volatile("ldmatrix.sync.aligned.m8n8.x4.shared.b16 {%0,%1,%2,%3}, [%4];"
                 : "=r"(r[0]), "=r"(r[1]), "=r"(r[2]), "=r"(r[3]) : "r"(addr));
}
__device__ __forceinline__ void ldm4t(uint32_t* r, uint32_t addr) {
    asm volatile("ldmatrix.sync.aligned.m8n8.x4.trans.shared.b16 {%0,%1,%2,%3}, [%4];"
                 : "=r"(r[0]), "=r"(r[1]), "=r"(r[2]), "=r"(r[3]) : "r"(addr));
}
__device__ __forceinline__ void mma16(float* c, const uint32_t* a, const uint32_t* b) {
    asm volatile("mma.sync.aligned.m16n8k16.row.col.f32.f16.f16.f32 "
        "{%0,%1,%2,%3},{%4,%5,%6,%7},{%8,%9},{%0,%1,%2,%3};"
        : "+f"(c[0]), "+f"(c[1]), "+f"(c[2]), "+f"(c[3])
        : "r"(a[0]), "r"(a[1]), "r"(a[2]), "r"(a[3]), "r"(b[0]), "r"(b[1]));
}
#define CPA16(dst, src) \
    asm volatile("cp.async.cg.shared.global [%0], [%1], 16;" :: "r"(dst), "l"(src) : "memory")

// ============================================================================
// fp16 GEMM: block 128x128, 8 warps (64x32), ktile 64, 3-stage, 1 sync/ktile.
// MODE: 0=qkv, 1=dots(split-K=2), 2=O trans-B, 3=out, 4=ksw (fused sw-reduce)
// ============================================================================
template<int MODE, int KT>
__global__ __launch_bounds__(256) void g16(const float* __restrict__ auxA,
                                           float* __restrict__ outp) {
    extern __shared__ __half sh[];
    __half* AsB = sh;
    __half* BsB = sh + 3 * ASTG_H;
    const int t = threadIdx.x, lane = t & 31, warp = t >> 5;
    const int bx = blockIdx.x, by = blockIdx.y;
    const int h = (MODE == 1) ? (blockIdx.z & 7) : blockIdx.z;
    const int split = (MODE == 1) ? (blockIdx.z >> 3) : 0;

    const __half *A, *B; int lda, ldb;
    if (MODE == 0)      { A = g_xh + (size_t)by * 128 * 128; lda = 128;
                          B = g_wt + (size_t)bx * 128 * 128; ldb = 128; }
    else if (MODE == 4) { A = g_xh + (size_t)by * 128 * 128; lda = 128;
                          B = g_wt + (size_t)768 * 128;      ldb = 128; }
    else if (MODE == 1) { A = g_qh + ((size_t)h * 512 + by * 128) * 4096 + split * 2048; lda = 4096;
                          B = g_kh + ((size_t)h * 512 + bx * 128) * 4096 + split * 2048; ldb = 4096; }
    else if (MODE == 2) { A = g_ph + ((size_t)h * 512 + by * 128) * 512; lda = 512;
                          B = g_vh + (size_t)h * 512 * 4096 + bx * 128;  ldb = 4096; }
    else                { A = g_o2 + (size_t)by * 128 * 256; lda = 256;
                          B = g_woutt;                       ldb = 256; }

    auto cpst = [&](int st, int k0) {
        uint32_t da = smem_u32(AsB + st * ASTG_H), db = smem_u32(BsB + st * ASTG_H);
#pragma unroll
        for (int c = t; c < 1024; c += 256) {
            int row = c >> 3, col = c & 7;
            CPA16(da + row * 144 + col * 16, A + (size_t)row * lda + k0 + col * 8);
        }
        if (MODE == 2) {
#pragma unroll
            for (int c = t; c < 1024; c += 256) {
                int row = c >> 4, col = c & 15;
                CPA16(db + row * 272 + col * 16, B + (size_t)(k0 + row) * ldb + col * 8);
            }
        } else {
#pragma unroll
            for (int c = t; c < 1024; c += 256) {
                int row = c >> 3, col = c & 7;
                CPA16(db + row * 144 + col * 16, B + (size_t)row * ldb + k0 + col * 8);
            }
        }
        asm volatile("cp.async.commit_group;" ::: "memory");
    };

    float acc[4][4][4] = {};
    const int wm0 = (warp >> 2) * 64, wn0 = (warp & 3) * 32;
    const int q = lane >> 3;

    cpst(0, 0);
    if (KT > 1) cpst(1, 64);
    int st = 0;
    for (int kt = 0; kt < KT; kt++) {
        if (kt + 1 < KT) asm volatile("cp.async.wait_group 1;" ::: "memory");
        else             asm volatile("cp.async.wait_group 0;" ::: "memory");
        __syncthreads();
        uint32_t ab = smem_u32(AsB + st * ASTG_H), bb = smem_u32(BsB + st * ASTG_H);
#pragma unroll
        for (int kk = 0; kk < 64; kk += 16) {
            uint32_t af[4][4], bf[2][4];
#pragma unroll
            for (int mt = 0; mt < 4; mt++)
                ldm4(af[mt], ab + (wm0 + mt * 16 + (lane & 15)) * 144 + (kk + (lane >> 4) * 8) * 2);
#pragma unroll
            for (int np = 0; np < 2; np++) {
                if (MODE == 2)
                    ldm4t(bf[np], bb + (kk + (q & 1) * 8 + (lane & 7)) * 272
                                     + (wn0 + np * 16 + (q >> 1) * 8) * 2);
                else
                    ldm4(bf[np], bb + (wn0 + np * 16 + (q >> 1) * 8 + (lane & 7)) * 144
                                    + (kk + (q & 1) * 8) * 2);
            }
#pragma unroll
            for (int mt = 0; mt < 4; mt++)
#pragma unroll
                for (int nt = 0; nt < 4; nt++)
                    mma16(acc[mt][nt], af[mt], &bf[nt >> 1][(nt & 1) * 2]);
        }
        if (kt + 2 < KT) {
            int ns = st + 2; if (ns >= 3) ns -= 3;
            cpst(ns, (kt + 2) * 64);
        }
        st = (st == 2) ? 0 : st + 1;
    }

    if (MODE == 4) {
        // fused soft-weight reduce: sw[n,h,r] = sum_d (ksw[m,c]+bias)*qsw[n,c] / 4
#pragma unroll
        for (int mt = 0; mt < 4; mt++)
#pragma unroll
            for (int hf = 0; hf < 2; hf++) {
                int mrow = wm0 + mt * 16 + (lane >> 2) + hf * 8;
                int m = by * 128 + mrow, r = m >> 9, n = m & 511;
                float p[2] = {0.f, 0.f};
#pragma unroll
                for (int nt = 0; nt < 4; nt++) {
                    int c = wn0 + nt * 8 + (lane & 3) * 2;
                    float v0 = acc[mt][nt][hf * 2]     + auxA[c];
                    float v1 = acc[mt][nt][hf * 2 + 1] + auxA[c + 1];
                    p[nt >> 1] += v0 * g_qsw[n * 128 + c] + v1 * g_qsw[n * 128 + c + 1];
                }
#pragma unroll
                for (int hi = 0; hi < 2; hi++) {
                    p[hi] += __shfl_xor_sync(0xffffffffu, p[hi], 1);
                    p[hi] += __shfl_xor_sync(0xffffffffu, p[hi], 2);
                }
                if ((lane & 3) == 0) {
                    int h0 = wn0 >> 4;
                    g_wrow[(n * 8 + h0) * 128 + r]       = p[0] * 0.25f;
                    g_wrow[(n * 8 + h0 + 1) * 128 + r]   = p[1] * 0.25f;
                }
            }
        return;
    }

#pragma unroll
    for (int mt = 0; mt < 4; mt++)
#pragma unroll
        for (int nt = 0; nt < 4; nt++)
#pragma unroll
            for (int hf = 0; hf < 2; hf++) {
                int mrow = wm0 + mt * 16 + (lane >> 2) + hf * 8;
                int ncol = wn0 + nt * 8 + (lane & 3) * 2;
                float v0 = acc[mt][nt][hf * 2], v1 = acc[mt][nt][hf * 2 + 1];
                if (MODE == 0) {
                    int m = by * 128 + mrow, c = bx * 128 + ncol;
                    int r = m >> 9, n = m & 511;
                    if (c < 256) {
                        int hh = c >> 5, d = c & 31;
                        float w = g_wrow[(n * 8 + hh) * 128 + r];
                        *reinterpret_cast<__half2*>(
                            &g_qh[((size_t)(hh * 512 + n)) * 4096 + r * 32 + d]) =
                            __floats2half2_rn(v0 * w, v1 * w);
                    } else if (c < 512) {
                        int cc = c - 256, hh = cc >> 5, d = cc & 31;
                        *reinterpret_cast<__half2*>(
                            &g_kh[((size_t)(hh * 512 + n)) * 4096 + r * 32 + d]) =
                            __floats2half2_rn(v0, v1);
                    } else {
                        int cc = c - 512, hh = cc >> 5, d = cc & 31;
                        *reinterpret_cast<__half2*>(
                            &g_vh[((size_t)(hh * 512 + n)) * 4096 + r * 32 + d]) =
                            __floats2half2_rn(v0, v1);
                    }
                } else if (MODE == 1) {
                    int i = by * 128 + mrow, j = bx * 128 + ncol;
                    size_t off = (size_t)split * DPL + ((size_t)h * 512 + i) * 512 + j;
                    g_dots[off]     = v0;
                    g_dots[off + 1] = v1;
                } else if (MODE == 2) {
                    int i = by * 128 + mrow, tcol = bx * 128 + ncol;
                    int r = tcol >> 5, d = tcol & 31;
                    *reinterpret_cast<__half2*>(
                        &g_o2[((size_t)r * 512 + i) * 256 + h * 32 + d]) =
                        __floats2half2_rn(v0, v1);
                } else {
                    int m = by * 128 + mrow;
                    outp[(size_t)m * 128 + ncol]     = v0 + auxA[ncol];
                    outp[(size_t)m * 128 + ncol + 1] = v1 + auxA[ncol + 1];
                }
            }
}

// ============================================================================
// pbh: LN(pair_bias) @ Wpair.  Warp per row, 2 rows/iter, split-tree reduce.
// ============================================================================
__global__ __launch_bounds__(256) void pbh_kernel(const float* __restrict__ pair_bias,
                                                  const float* __restrict__ ln_g,
                                                  const float* __restrict__ ln_b,
                                                  const float* __restrict__ Wpair) {
    const int lane = threadIdx.x & 31;
    const int gw = (blockIdx.x * 256 + threadIdx.x) >> 5;
    const int nw = (gridDim.x * 256) >> 5;
    const int p0 = lane * 4;

    float gg[4], bb4[4], wp[4][8];
#pragma unroll
    for (int e = 0; e < 4; e++) {
        gg[e]  = ln_g[p0 + e];
        bb4[e] = ln_b[p0 + e];
        float4 w0 = *reinterpret_cast<const float4*>(&Wpair[(p0 + e) * 8]);
        float4 w1 = *reinterpret_cast<const float4*>(&Wpair[(p0 + e) * 8 + 4]);
        wp[e][0] = w0.x; wp[e][1] = w0.y; wp[e][2] = w0.z; wp[e][3] = w0.w;
        wp[e][4] = w1.x; wp[e][5] = w1.y; wp[e][6] = w1.z; wp[e][7] = w1.w;
    }
    const int myh = ((lane >> 4) & 1) * 4 + ((lane >> 3) & 1) * 2 + ((lane >> 2) & 1);
    const bool writer = (lane & 3) == 0;

    for (int idx = gw * 2; idx < NN * NN; idx += nw * 2) {
        float4 va = *reinterpret_cast<const float4*>(&pair_bias[(size_t)idx * 128 + p0]);
        float4 vb = *reinterpret_cast<const float4*>(&pair_bias[(size_t)(idx + 1) * 128 + p0]);
        float vv[2][4] = {{va.x, va.y, va.z, va.w}, {vb.x, vb.y, vb.z, vb.w}};
        float s[2], sq[2];
#pragma unroll
        for (int rr = 0; rr < 2; rr++) {
            s[rr]  = vv[rr][0] + vv[rr][1] + vv[rr][2] + vv[rr][3];
            sq[rr] = vv[rr][0] * vv[rr][0] + vv[rr][1] * vv[rr][1]
                   + vv[rr][2] * vv[rr][2] + vv[rr][3] * vv[rr][3];
        }
#pragma unroll
        for (int o = 16; o; o >>= 1) {
#pragma unroll
            for (int rr = 0; rr < 2; rr++) {
                s[rr]  += __shfl_xor_sync(0xffffffffu, s[rr], o);
                sq[rr] += __shfl_xor_sync(0xffffffffu, sq[rr], o);
            }
        }
        float ph[2][8] = {};
#pragma unroll
        for (int rr = 0; rr < 2; rr++) {
            float mean = s[rr] * (1.0f / 128.0f);
            float var  = sq[rr] * (1.0f / 128.0f) - mean * mean;
            float rstd = rsqrtf(var + 1e-5f);
#pragma unroll
            for (int e = 0; e < 4; e++) {
                float nz = (vv[rr][e] - mean) * rstd * gg[e] + bb4[e];
#pragma unroll
                for (int hh = 0; hh < 8; hh++) ph[rr][hh] += nz * wp[e][hh];
            }
        }
#pragma unroll
        for (int rr = 0; rr < 2; rr++) {
            float* v = ph[rr];
#pragma unroll
            for (int hh = 0; hh < 8; hh++) v[hh] += __shfl_xor_sync(0xffffffffu, v[hh], 16);
            if (lane & 16) { v[0] = v[4]; v[1] = v[5]; v[2] = v[6]; v[3] = v[7]; }
#pragma unroll
            for (int hh = 0; hh < 4; hh++) v[hh] += __shfl_xor_sync(0xffffffffu, v[hh], 8);
            if (lane & 8) { v[0] = v[2]; v[1] = v[3]; }
#pragma unroll
            for (int hh = 0; hh < 2; hh++) v[hh] += __shfl_xor_sync(0xffffffffu, v[hh], 4);
            if (lane & 4) { v[0] = v[1]; }
            v[0] += __shfl_xor_sync(0xffffffffu, v[0], 2);
            v[0] += __shfl_xor_sync(0xffffffffu, v[0], 1);
        }
        if (writer) {
            int i0 = idx >> 9, j0 = idx & 511;
            int i1 = (idx + 1) >> 9, j1 = (idx + 1) & 511;
            g_pbh[(((size_t)myh << 9) + i0) * NN + j0] = ph[0][0];
            g_pbh[(((size_t)myh << 9) + i1) * NN + j1] = ph[1][0];
        }
    }
}

// ============================================================================
__global__ void conv_x(const float* __restrict__ x) {
    size_t i = ((size_t)blockIdx.x * 256 + threadIdx.x) * 4;
    float4 v = *reinterpret_cast<const float4*>(x + i);
    __half2* d = reinterpret_cast<__half2*>(&g_xh[i]);
    d[0] = __floats2half2_rn(v.x, v.y);
    d[1] = __floats2half2_rn(v.z, v.w);
}

__global__ void conv_w(const float* __restrict__ Wq, const float* __restrict__ Wkv,
                       const float* __restrict__ Wk_sw, const float* __restrict__ Wout) {
    int g = blockIdx.x * 256 + threadIdx.x;
    if (g < 114688) {
        int row = g >> 7, k = g & 127;
        float v;
        if (row < 256)      v = Wq[k * 256 + row];
        else if (row < 768) v = Wkv[k * 512 + (row - 256)];
        else                v = Wk_sw[k * 128 + (row - 768)];
        g_wt[g] = __float2half_rn(v);
    } else {
        int g2 = g - 114688;
        int c = g2 >> 8, k = g2 & 255;
        g_woutt[g2] = __float2half_rn(Wout[k * 128 + c]);
    }
}

__global__ void qsw_kernel(const float* __restrict__ x, const float* __restrict__ Wq_sw,
                           const float* __restrict__ bq_sw) {
    int n = blockIdx.x, c = threadIdx.x;
    __shared__ float xr[128];
    xr[c] = x[(size_t)n * 128 + c];
    __syncthreads();
    float acc = bq_sw[c];
#pragma unroll 8
    for (int k = 0; k < 128; k++) acc += xr[k] * Wq_sw[k * 128 + c];
    g_qsw[n * 128 + c] = acc;
}

__global__ void wrow_softmax_kernel() {
    int row = blockIdx.x, t = threadIdx.x;
    float v = g_wrow[(size_t)row * 128 + t];
    __shared__ float sm[128];
    sm[t] = v; __syncthreads();
#pragma unroll
    for (int s = 64; s > 0; s >>= 1) { if (t < s) sm[t] = fmaxf(sm[t], sm[t + s]); __syncthreads(); }
    float mx = sm[0]; __syncthreads();
    float e = expf(v - mx);
    sm[t] = e; __syncthreads();
#pragma unroll
    for (int s = 64; s > 0; s >>= 1) { if (t < s) sm[t] += sm[t + s]; __syncthreads(); }
    g_wrow[(size_t)row * 128 + t] = e / sm[0];
}

__global__ void attn_softmax_kernel() {
    size_t row = blockIdx.x;
    int t = threadIdx.x;
    size_t off0 = row * 512 + t, off1 = off0 + 256;
    const float scale = 0.17677669529663687f;
    float v0 = (g_dots[off0] + g_dots[off0 + DPL]) * scale + g_pbh[off0];
    float v1 = (g_dots[off1] + g_dots[off1 + DPL]) * scale + g_pbh[off1];
    __shared__ float sm[256];
    sm[t] = fmaxf(v0, v1); __syncthreads();
#pragma unroll
    for (int s = 128; s > 0; s >>= 1) { if (t < s) sm[t] = fmaxf(sm[t], sm[t + s]); __syncthreads(); }
    float mx = sm[0]; __syncthreads();
    float e0 = expf(v0 - mx), e1 = expf(v1 - mx);
    sm[t] = e0 + e1; __syncthreads();
#pragma unroll
    for (int s = 128; s > 0; s >>= 1) { if (t < s) sm[t] += sm[t + s]; __syncthreads(); }
    float inv = 1.0f / sm[0];
    g_ph[row * 512 + t]       = __float2half_rn(e0 * inv);
    g_ph[row * 512 + t + 256] = __float2half_rn(e1 * inv);
}

// ============================================================================
extern "C" void kernel_launch(void* const* d_in, const int* in_sizes, int n_in,
                              void* d_out, int out_size) {
    (void)in_sizes; (void)n_in; (void)out_size;
    const float* x         = (const float*)d_in[0];
    const float* pair_bias = (const float*)d_in[1];
    const float* Wq        = (const float*)d_in[2];
    const float* Wkv       = (const float*)d_in[3];
    const float* Wout      = (const float*)d_in[4];
    const float* b_out     = (const float*)d_in[5];
    const float* ln_g      = (const float*)d_in[6];
    const float* ln_b      = (const float*)d_in[7];
    const float* Wpair     = (const float*)d_in[8];
    const float* Wq_sw     = (const float*)d_in[9];
    const float* bq_sw     = (const float*)d_in[10];
    const float* Wk_sw     = (const float*)d_in[11];
    const float* bk_sw     = (const float*)d_in[12];
    float* out = (float*)d_out;

    static int attr_done = 0;
    if (!attr_done) {
        cudaFuncSetAttribute(g16<0, 2>,  cudaFuncAttributeMaxDynamicSharedMemorySize, SMEM_BYTES);
        cudaFuncSetAttribute(g16<1, 32>, cudaFuncAttributeMaxDynamicSharedMemorySize, SMEM_BYTES);
        cudaFuncSetAttribute(g16<2, 8>,  cudaFuncAttributeMaxDynamicSharedMemorySize, SMEM_BYTES);
        cudaFuncSetAttribute(g16<3, 4>,  cudaFuncAttributeMaxDynamicSharedMemorySize, SMEM_BYTES);
        cudaFuncSetAttribute(g16<4, 2>,  cudaFuncAttributeMaxDynamicSharedMemorySize, SMEM_BYTES);
        attr_done = 1;
    }

    conv_x             <<<8192, 256>>>(x);
    conv_w             <<<576, 256>>>(Wq, Wkv, Wk_sw, Wout);
    qsw_kernel         <<<NN, 128>>>(x, Wq_sw, bq_sw);
    pbh_kernel         <<<2048, 256>>>(pair_bias, ln_g, ln_b, Wpair);        // 4th: profiled
    g16<4, 2>          <<<dim3(1, 512), 256, SMEM_BYTES>>>(bk_sw, nullptr);  // ksw + fused reduce
    wrow_softmax_kernel<<<NN * HH, 128>>>();
    g16<0, 2>          <<<dim3(6, 512), 256, SMEM_BYTES>>>(nullptr, nullptr);   // qkv
    g16<1, 32>         <<<dim3(4, 4, 16), 256, SMEM_BYTES>>>(nullptr, nullptr); // dots sK=2
    attn_softmax_kernel<<<HH * NN, 256>>>();
    g16<2, 8>          <<<dim3(32, 4, 8), 256, SMEM_BYTES>>>(nullptr, nullptr); // O
    g16<3, 4>          <<<dim3(1, 512), 256, SMEM_BYTES>>>(b_out, out);         // out
}